// round 5
// baseline (speedup 1.0000x reference)
#include <cuda_runtime.h>
#include <cstdint>
#include <cstddef>

#define B_ 16
#define LK_ 8192
#define D_ 1024
#define H_ 1024
#define M_TOTAL (B_*LK_)

#define TM 128
#define TN 128
#define TK 16
#define SBN 136            // B row stride (floats): 136%32=8 -> t shifts banks, conflict-free LDS.128
#define NSTAGE 4
#define NCH (H_/TN)        // 8
#define KST (D_/TK)        // 64
#define TOTS (KST*NCH)     // 512 flat stages

#define A_STG (TM*TK)      // 2048 floats per A stage (no pad; 16-float rows)
#define B_STG (TK*SBN)     // 2176 floats per B stage
#define SMEM_FLOATS (NSTAGE*A_STG + NSTAGE*B_STG + TN + TN + TM*4)
#define SMEM_BYTES (SMEM_FLOATS*4)

// ---- device scratch (allowed: __device__ globals, no runtime allocation) ----
__device__ float g_qp[B_*H_];
__device__ float g_keysR[(size_t)M_TOTAL * D_];   // tf32-rounded keys (512 MB)
__device__ float g_WkR[D_*H_];                    // tf32-rounded W_k (4 MB)

// ---------------- rounding pass: fp32 -> tf32(RNA)-in-fp32 ----------------
__device__ __forceinline__ float tf32r(float f) {
    uint32_t r; asm("cvt.rna.tf32.f32 %0, %1;" : "=r"(r) : "f"(f));
    return __uint_as_float(r);
}

__global__ __launch_bounds__(256) void round_keys_kernel(const float4* __restrict__ in) {
    float4* out = (float4*)g_keysR;
    const int n4 = M_TOTAL * (D_ / 4);
    for (int i = blockIdx.x * 256 + threadIdx.x; i < n4; i += gridDim.x * 256) {
        float4 v = in[i];
        out[i] = make_float4(tf32r(v.x), tf32r(v.y), tf32r(v.z), tf32r(v.w));
    }
}

__global__ __launch_bounds__(256) void round_wk_kernel(const float4* __restrict__ in) {
    float4* out = (float4*)g_WkR;
    const int n4 = D_ * H_ / 4;
    for (int i = blockIdx.x * 256 + threadIdx.x; i < n4; i += gridDim.x * 256) {
        float4 v = in[i];
        out[i] = make_float4(tf32r(v.x), tf32r(v.y), tf32r(v.z), tf32r(v.w));
    }
}

// ---------------- qp[b,h] = sum_d queries[b,0,d] * W_q[d,h] (full fp32) ----------------
__global__ __launch_bounds__(256) void qproj_kernel(const float* __restrict__ q,
                                                    const float* __restrict__ Wq) {
    int b = blockIdx.y;
    int h = blockIdx.x * 256 + threadIdx.x;
    const float* qr = q + b * D_;
    float acc = 0.f;
#pragma unroll 8
    for (int d = 0; d < D_; ++d) acc = fmaf(qr[d], Wq[d * H_ + h], acc);
    g_qp[b * H_ + h] = acc;
}

// ---------------- helpers ----------------
__device__ __forceinline__ void cp4(float* dst, const float* src) {
    uint32_t d = (uint32_t)__cvta_generic_to_shared(dst);
    asm volatile("cp.async.ca.shared.global [%0], [%1], 4;\n" :: "r"(d), "l"(src));
}

__device__ __forceinline__ float tanh_hw(float x) {
    float r; asm("tanh.approx.f32 %0, %1;" : "=f"(r) : "f"(x)); return r;
}

// one mma.m16n8k8 tf32 (operands are pre-rounded tf32 bit patterns)
__device__ __forceinline__ void mma8(float* acc, float a0, float a1, float a2, float a3,
                                     float b0, float b1) {
    asm volatile(
        "mma.sync.aligned.m16n8k8.row.col.f32.tf32.tf32.f32 "
        "{%0,%1,%2,%3},{%4,%5,%6,%7},{%8,%9},{%0,%1,%2,%3};"
        : "+f"(acc[0]), "+f"(acc[1]), "+f"(acc[2]), "+f"(acc[3])
        : "r"(__float_as_uint(a0)), "r"(__float_as_uint(a1)),
          "r"(__float_as_uint(a2)), "r"(__float_as_uint(a3)),
          "r"(__float_as_uint(b0)), "r"(__float_as_uint(b1)));
}

// stage fill with permuted layouts:
//   A[row][k'] where k' = (k%4)*4 + k/4   (so lds128 at 4t gives k = {t,t+4,t+8,t+12})
//   B[k][p]   where p  = (c&96) + (c&7)*4 + ((c>>3)&3)   (so lds128 at wn*32+4g gives ni=0..3)
__device__ __forceinline__ void load_stage(float* __restrict__ sA, float* __restrict__ sB,
                                           int m_base, int s, int tid) {
    const int nc = s >> 6;
    const int k0 = (s & 63) * TK;
    const float* __restrict__ keysR = g_keysR;
    const float* __restrict__ WkR = g_WkR;
#pragma unroll
    for (int i = 0; i < 8; ++i) {
        int c = tid + i * 256;             // 0..2047
        int row = c >> 4, kp = c & 15;
        cp4(sA + row * TK + kp,
            keysR + (size_t)(m_base + row) * D_ + k0 + ((kp & 3) << 2) + (kp >> 2));
    }
#pragma unroll
    for (int i = 0; i < 8; ++i) {
        int c = tid + i * 256;             // 0..2047
        int row = c >> 7, col = c & 127;
        int p = (col & 96) + ((col & 7) << 2) + ((col >> 3) & 3);
        cp4(sB + row * SBN + p,
            WkR + (size_t)(k0 + row) * H_ + nc * TN + col);
    }
}

// ---------------- fused keys@W_k -> tanh -> dot(w_v) ----------------
__global__ void __launch_bounds__(256, 2) attn_kernel(const float* __restrict__ wv,
                                                      float* __restrict__ out) {
    extern __shared__ float sm[];
    float* sAbase  = sm;                                   // NSTAGE * 2048
    float* sBbase  = sm + NSTAGE * A_STG;                  // NSTAGE * 2176
    float* s_qp    = sm + NSTAGE * A_STG + NSTAGE * B_STG; // 128
    float* s_wv    = s_qp + TN;                            // 128
    float* s_red   = s_wv + TN;                            // 128*4

    const int tid  = threadIdx.x;
    const int lane = tid & 31, warp = tid >> 5;
    const int wm = warp >> 2, wn = warp & 3;               // 2x4 warp grid, warp tile 64x32
    const int g = lane >> 2, t = lane & 3;
    const int m_base = blockIdx.x * TM;
    const int b = m_base >> 13;

    float score = 0.f;                                      // per-row (tid<128) accumulator

    if (tid < TN) { s_qp[tid] = g_qp[b * H_ + tid]; s_wv[tid] = wv[tid]; }

    // prologue: stages 0..2
#pragma unroll
    for (int s = 0; s < NSTAGE - 1; ++s) {
        load_stage(sAbase + s * A_STG, sBbase + s * B_STG, m_base, s, tid);
        asm volatile("cp.async.commit_group;\n");
    }

    float acc[4][4][4];
#pragma unroll
    for (int mi = 0; mi < 4; ++mi)
#pragma unroll
        for (int ni = 0; ni < 4; ++ni)
#pragma unroll
            for (int r = 0; r < 4; ++r) acc[mi][ni][r] = 0.f;

    const int bcol = wn * 32 + 4 * g;

    for (int s = 0; s < TOTS; ++s) {
        asm volatile("cp.async.wait_group %0;\n" :: "n"(NSTAGE - 2));
        __syncthreads();
        const int buf = s & (NSTAGE - 1);
        const float* sA = sAbase + buf * A_STG;
        const float* sB = sBbase + buf * B_STG;

        // B fragments: rows {t,t+4} (k8=0), {8+t,12+t} (k8=1); components = ni
        float4 fb00 = *(const float4*)(sB + (t     ) * SBN + bcol);
        float4 fb01 = *(const float4*)(sB + (t +  4) * SBN + bcol);
        float4 fb10 = *(const float4*)(sB + (t +  8) * SBN + bcol);
        float4 fb11 = *(const float4*)(sB + (t + 12) * SBN + bcol);

#pragma unroll
        for (int mi = 0; mi < 4; ++mi) {
            int mr = wm * 64 + mi * 16 + g;
            float4 fa0 = *(const float4*)(sA + mr * TK + 4 * t);        // rows mr
            float4 fa1 = *(const float4*)(sA + (mr + 8) * TK + 4 * t);  // rows mr+8
            // k8 = 0: a = {A[mr][t], A[mr+8][t], A[mr][t+4], A[mr+8][t+4]}
            mma8(acc[mi][0], fa0.x, fa1.x, fa0.y, fa1.y, fb00.x, fb01.x);
            mma8(acc[mi][1], fa0.x, fa1.x, fa0.y, fa1.y, fb00.y, fb01.y);
            mma8(acc[mi][2], fa0.x, fa1.x, fa0.y, fa1.y, fb00.z, fb01.z);
            mma8(acc[mi][3], fa0.x, fa1.x, fa0.y, fa1.y, fb00.w, fb01.w);
            // k8 = 1
            mma8(acc[mi][0], fa0.z, fa1.z, fa0.w, fa1.w, fb10.x, fb11.x);
            mma8(acc[mi][1], fa0.z, fa1.z, fa0.w, fa1.w, fb10.y, fb11.y);
            mma8(acc[mi][2], fa0.z, fa1.z, fa0.w, fa1.w, fb10.z, fb11.z);
            mma8(acc[mi][3], fa0.z, fa1.z, fa0.w, fa1.w, fb10.w, fb11.w);
        }

        if (s + NSTAGE - 1 < TOTS) {
            int sn = s + NSTAGE - 1;
            load_stage(sAbase + (sn & (NSTAGE - 1)) * A_STG,
                       sBbase + (sn & (NSTAGE - 1)) * B_STG, m_base, sn, tid);
        }
        asm volatile("cp.async.commit_group;\n");

        if ((s & 63) == 63) {
            // epilogue for h-chunk nc: tanh(qp + acc) * wv, reduce, accumulate
            const int nc = s >> 6;
#pragma unroll
            for (int mi = 0; mi < 4; ++mi) {
                float p0 = 0.f, p1 = 0.f;
#pragma unroll
                for (int ni = 0; ni < 4; ++ni) {
                    int c0 = wn * 32 + ni * 8 + 2 * t;
                    float q0 = s_qp[c0], q1 = s_qp[c0 + 1];
                    float w0 = s_wv[c0], w1 = s_wv[c0 + 1];
                    p0 += tanh_hw(q0 + acc[mi][ni][0]) * w0
                        + tanh_hw(q1 + acc[mi][ni][1]) * w1;
                    p1 += tanh_hw(q0 + acc[mi][ni][2]) * w0
                        + tanh_hw(q1 + acc[mi][ni][3]) * w1;
                    acc[mi][ni][0] = 0.f; acc[mi][ni][1] = 0.f;
                    acc[mi][ni][2] = 0.f; acc[mi][ni][3] = 0.f;
                }
                p0 += __shfl_xor_sync(0xffffffffu, p0, 1);
                p0 += __shfl_xor_sync(0xffffffffu, p0, 2);
                p1 += __shfl_xor_sync(0xffffffffu, p1, 1);
                p1 += __shfl_xor_sync(0xffffffffu, p1, 2);
                if (t == 0) {
                    int r0 = wm * 64 + mi * 16 + g;
                    s_red[(r0    ) * 4 + wn] = p0;
                    s_red[(r0 + 8) * 4 + wn] = p1;
                }
            }
            __syncthreads();   // s_red ready; also fences all s_qp/s_wv reads above
            if (tid < TM)
                score += s_red[tid * 4 + 0] + s_red[tid * 4 + 1]
                       + s_red[tid * 4 + 2] + s_red[tid * 4 + 3];
            if (nc + 1 < NCH && tid < TN) {
                s_qp[tid] = g_qp[b * H_ + (nc + 1) * TN + tid];
                s_wv[tid] = wv[(nc + 1) * TN + tid];
            }
            // (per-stage __syncthreads at top of next iteration orders these writes)
        }
    }

    asm volatile("cp.async.wait_group 0;\n");
    if (tid < TM) out[m_base + tid] = score;
}

// ---------------- launch ----------------
extern "C" void kernel_launch(void* const* d_in, const int* in_sizes, int n_in,
                              void* d_out, int out_size) {
    (void)in_sizes; (void)n_in; (void)out_size;
    const float* queries = (const float*)d_in[0];   // [16,1,1024]
    const float* keys    = (const float*)d_in[1];   // [16,8192,1024]
    const float* Wq      = (const float*)d_in[2];   // [1024,1024]
    const float* Wk      = (const float*)d_in[3];   // [1024,1024]
    const float* wv      = (const float*)d_in[4];   // [1024,1]
    float* out = (float*)d_out;                     // [16,8192]

    cudaFuncSetAttribute(attn_kernel, cudaFuncAttributeMaxDynamicSharedMemorySize, SMEM_BYTES);

    round_keys_kernel<<<4096, 256>>>((const float4*)keys);
    round_wk_kernel<<<512, 256>>>((const float4*)Wk);
    qproj_kernel<<<dim3(H_ / 256, B_), 256>>>(queries, Wq);
    attn_kernel<<<M_TOTAL / TM, 256, SMEM_BYTES>>>(wv, out);
}

// round 6
// speedup vs baseline: 1.3233x; 1.3233x over previous
#include <cuda_runtime.h>
#include <cstdint>
#include <cstddef>

#define B_ 16
#define LK_ 8192
#define D_ 1024
#define H_ 1024
#define M_TOTAL (B_*LK_)

#define TM 128
#define TN 128
#define TK 16
#define SBN 136            // B row stride (floats): conflict-free LDS.128 (banks 8t+4g+c)
#define NSTAGE 4
#define NCH (H_/TN)        // 8
#define KST (D_/TK)        // 64
#define TOTS (KST*NCH)     // 512 flat stages

#define A_STG (TM*TK)      // 2048 floats per A stage
#define B_STG (TK*SBN)     // 2176 floats per B stage (8704 B, 16B multiple)
#define SMEM_FLOATS (NSTAGE*A_STG + NSTAGE*B_STG + TN + TN + TM*4)
#define SMEM_BYTES (SMEM_FLOATS*4)

// ---- device scratch (__device__ globals; zero-initialized at load) ----
__device__ float g_qp[B_*H_];
// keys, tf32-rounded AND pre-permuted into smem-stage layout:
//   [m_tile 0..1023][ks 0..63][2048 floats = row*16 + kperm]
__device__ float g_keysA[(size_t)M_TOTAL * D_];
// W_k, tf32-rounded AND pre-permuted, stage-major with padding baked in:
//   [s 0..511][2176 floats = krow*136 + p(col)]
__device__ float g_WkB[(size_t)TOTS * B_STG];

// ---------------- helpers ----------------
__device__ __forceinline__ float tf32r(float f) {
    uint32_t r; asm("cvt.rna.tf32.f32 %0, %1;" : "=r"(r) : "f"(f));
    return __uint_as_float(r);
}
__device__ __forceinline__ void cp16(float* dst, const float* src) {
    uint32_t d = (uint32_t)__cvta_generic_to_shared(dst);
    asm volatile("cp.async.cg.shared.global [%0], [%1], 16;\n" :: "r"(d), "l"(src));
}
__device__ __forceinline__ float tanh_hw(float x) {
    float r; asm("tanh.approx.f32 %0, %1;" : "=f"(r) : "f"(x)); return r;
}
__device__ __forceinline__ void mma8(float* acc, float a0, float a1, float a2, float a3,
                                     float b0, float b1) {
    asm volatile(
        "mma.sync.aligned.m16n8k8.row.col.f32.tf32.tf32.f32 "
        "{%0,%1,%2,%3},{%4,%5,%6,%7},{%8,%9},{%0,%1,%2,%3};"
        : "+f"(acc[0]), "+f"(acc[1]), "+f"(acc[2]), "+f"(acc[3])
        : "r"(__float_as_uint(a0)), "r"(__float_as_uint(a1)),
          "r"(__float_as_uint(a2)), "r"(__float_as_uint(a3)),
          "r"(__float_as_uint(b0)), "r"(__float_as_uint(b1)));
}

// ---------------- one-time: round + permute keys into stage layout ----------------
// smem/scratch A position for (row r, local k): r*16 + (k&3)*4 + (k>>2)
// thread handles one source float4: k = 4q + j (j=0..3), local quad = q&3
__global__ __launch_bounds__(256) void round_permute_keys(const float4* __restrict__ in) {
    const int total = M_TOTAL * (D_ / 4);
    for (int idx = blockIdx.x * 256 + threadIdx.x; idx < total; idx += gridDim.x * 256) {
        int m = idx >> 8, q = idx & 255;
        float4 v = in[idx];
        float* dst = g_keysA + ((size_t)(m >> 7) * KST + (q >> 2)) * A_STG
                   + (m & 127) * TK + (q & 3);
        dst[0]  = tf32r(v.x);
        dst[4]  = tf32r(v.y);
        dst[8]  = tf32r(v.z);
        dst[12] = tf32r(v.w);
    }
}

// ---------------- one-time: round + permute W_k into stage layout ----------------
// p(col) = (col&96) + ((col&7)<<2) + ((col>>3)&3); pad cols 128..135 stay zero (never read)
__global__ __launch_bounds__(256) void round_permute_wk(const float* __restrict__ Wk) {
    int idx = blockIdx.x * 256 + threadIdx.x;          // 0 .. 1024*1024-1
    int srow = idx >> 10, scol = idx & 1023;
    int nc = scol >> 7, col = scol & 127;
    int s = nc * KST + (srow >> 4);
    int p = (col & 96) + ((col & 7) << 2) + ((col >> 3) & 3);
    g_WkB[(size_t)(s * TK + (srow & 15)) * SBN + p] = tf32r(Wk[idx]);
}

// ---------------- qp[b,h] = sum_d queries[b,0,d] * W_q[d,h] (full fp32) ----------------
__global__ __launch_bounds__(256) void qproj_kernel(const float* __restrict__ q,
                                                    const float* __restrict__ Wq) {
    int b = blockIdx.y;
    int h = blockIdx.x * 256 + threadIdx.x;
    const float* qr = q + b * D_;
    float acc = 0.f;
#pragma unroll 8
    for (int d = 0; d < D_; ++d) acc = fmaf(qr[d], Wq[d * H_ + h], acc);
    g_qp[b * H_ + h] = acc;
}

// linear stage fill: A 512 float4, B 544 float4, all 16B cp.async
__device__ __forceinline__ void load_stage(float* __restrict__ sAbase,
                                           float* __restrict__ sBbase,
                                           int m_tile, int sn, int tid) {
    const float* srcA = g_keysA + ((size_t)m_tile * KST + (sn & 63)) * A_STG;
    const float* srcB = g_WkB + (size_t)sn * B_STG;
    float* dA = sAbase + (sn & (NSTAGE - 1)) * A_STG;
    float* dB = sBbase + (sn & (NSTAGE - 1)) * B_STG;
    cp16(dA + tid * 4,          srcA + tid * 4);
    cp16(dA + (tid + 256) * 4,  srcA + (tid + 256) * 4);
    cp16(dB + tid * 4,          srcB + tid * 4);
    cp16(dB + (tid + 256) * 4,  srcB + (tid + 256) * 4);
    if (tid < 32) cp16(dB + (tid + 512) * 4, srcB + (tid + 512) * 4);
}

// ---------------- fused keys@W_k -> tanh -> dot(w_v) ----------------
__global__ void __launch_bounds__(256, 2) attn_kernel(const float* __restrict__ wv,
                                                      float* __restrict__ out) {
    extern __shared__ float sm[];
    float* sAbase = sm;                                    // NSTAGE * 2048
    float* sBbase = sm + NSTAGE * A_STG;                   // NSTAGE * 2176
    float* s_qp   = sm + NSTAGE * A_STG + NSTAGE * B_STG;  // 128
    float* s_wv   = s_qp + TN;                             // 128
    float* s_red  = s_wv + TN;                             // 128*4

    const int tid  = threadIdx.x;
    const int lane = tid & 31, warp = tid >> 5;
    const int wm = warp >> 2, wn = warp & 3;               // 2x4 warp grid, warp tile 64x32
    const int g = lane >> 2, t = lane & 3;
    const int m_tile = blockIdx.x;
    const int m_base = m_tile * TM;
    const int b = m_base >> 13;

    float score = 0.f;

    if (tid < TN) { s_qp[tid] = g_qp[b * H_ + tid]; s_wv[tid] = wv[tid]; }

#pragma unroll
    for (int s = 0; s < NSTAGE - 1; ++s) {
        load_stage(sAbase, sBbase, m_tile, s, tid);
        asm volatile("cp.async.commit_group;\n");
    }

    float acc[4][4][4];
#pragma unroll
    for (int mi = 0; mi < 4; ++mi)
#pragma unroll
        for (int ni = 0; ni < 4; ++ni)
#pragma unroll
            for (int r = 0; r < 4; ++r) acc[mi][ni][r] = 0.f;

    const int bcol = wn * 32 + 4 * g;

    for (int s = 0; s < TOTS; ++s) {
        asm volatile("cp.async.wait_group %0;\n" :: "n"(NSTAGE - 2));
        __syncthreads();

        // prefetch stage s+3 into the buffer freed at stage s-1 (issue early, overlap mma)
        if (s + NSTAGE - 1 < TOTS)
            load_stage(sAbase, sBbase, m_tile, s + NSTAGE - 1, tid);
        asm volatile("cp.async.commit_group;\n");

        const int buf = s & (NSTAGE - 1);
        const float* sA = sAbase + buf * A_STG;
        const float* sB = sBbase + buf * B_STG;

        // B fragments: rows {t,t+4} (k8=0), {t+8,t+12} (k8=1); float4 components = ni
        float4 fb00 = *(const float4*)(sB + (t     ) * SBN + bcol);
        float4 fb01 = *(const float4*)(sB + (t +  4) * SBN + bcol);
        float4 fb10 = *(const float4*)(sB + (t +  8) * SBN + bcol);
        float4 fb11 = *(const float4*)(sB + (t + 12) * SBN + bcol);

#pragma unroll
        for (int mi = 0; mi < 4; ++mi) {
            int mr = wm * 64 + mi * 16 + g;
            float4 fa0 = *(const float4*)(sA + mr * TK + 4 * t);        // rows mr
            float4 fa1 = *(const float4*)(sA + (mr + 8) * TK + 4 * t);  // rows mr+8
            // k8 = 0
            mma8(acc[mi][0], fa0.x, fa1.x, fa0.y, fa1.y, fb00.x, fb01.x);
            mma8(acc[mi][1], fa0.x, fa1.x, fa0.y, fa1.y, fb00.y, fb01.y);
            mma8(acc[mi][2], fa0.x, fa1.x, fa0.y, fa1.y, fb00.z, fb01.z);
            mma8(acc[mi][3], fa0.x, fa1.x, fa0.y, fa1.y, fb00.w, fb01.w);
            // k8 = 1
            mma8(acc[mi][0], fa0.z, fa1.z, fa0.w, fa1.w, fb10.x, fb11.x);
            mma8(acc[mi][1], fa0.z, fa1.z, fa0.w, fa1.w, fb10.y, fb11.y);
            mma8(acc[mi][2], fa0.z, fa1.z, fa0.w, fa1.w, fb10.z, fb11.z);
            mma8(acc[mi][3], fa0.z, fa1.z, fa0.w, fa1.w, fb10.w, fb11.w);
        }

        if ((s & 63) == 63) {
            // epilogue for h-chunk nc: tanh(qp + acc) * wv, reduce, accumulate
            const int nc = s >> 6;
#pragma unroll
            for (int mi = 0; mi < 4; ++mi) {
                float p0 = 0.f, p1 = 0.f;
#pragma unroll
                for (int ni = 0; ni < 4; ++ni) {
                    int c0 = wn * 32 + ni * 8 + 2 * t;
                    float q0 = s_qp[c0], q1 = s_qp[c0 + 1];
                    float w0 = s_wv[c0], w1 = s_wv[c0 + 1];
                    p0 += tanh_hw(q0 + acc[mi][ni][0]) * w0
                        + tanh_hw(q1 + acc[mi][ni][1]) * w1;
                    p1 += tanh_hw(q0 + acc[mi][ni][2]) * w0
                        + tanh_hw(q1 + acc[mi][ni][3]) * w1;
                    acc[mi][ni][0] = 0.f; acc[mi][ni][1] = 0.f;
                    acc[mi][ni][2] = 0.f; acc[mi][ni][3] = 0.f;
                }
                p0 += __shfl_xor_sync(0xffffffffu, p0, 1);
                p0 += __shfl_xor_sync(0xffffffffu, p0, 2);
                p1 += __shfl_xor_sync(0xffffffffu, p1, 1);
                p1 += __shfl_xor_sync(0xffffffffu, p1, 2);
                if (t == 0) {
                    int r0 = wm * 64 + mi * 16 + g;
                    s_red[(r0    ) * 4 + wn] = p0;
                    s_red[(r0 + 8) * 4 + wn] = p1;
                }
            }
            __syncthreads();   // s_red ready; fences s_qp/s_wv reads above
            if (tid < TM)
                score += s_red[tid * 4 + 0] + s_red[tid * 4 + 1]
                       + s_red[tid * 4 + 2] + s_red[tid * 4 + 3];
            if (nc + 1 < NCH && tid < TN) {
                s_qp[tid] = g_qp[b * H_ + (nc + 1) * TN + tid];
                s_wv[tid] = wv[(nc + 1) * TN + tid];
            }
            // next-iteration top __syncthreads orders these writes vs readers
        }
    }

    asm volatile("cp.async.wait_group 0;\n");
    if (tid < TM) out[m_base + tid] = score;
}

// ---------------- launch ----------------
extern "C" void kernel_launch(void* const* d_in, const int* in_sizes, int n_in,
                              void* d_out, int out_size) {
    (void)in_sizes; (void)n_in; (void)out_size;
    const float* queries = (const float*)d_in[0];   // [16,1,1024]
    const float* keys    = (const float*)d_in[1];   // [16,8192,1024]
    const float* Wq      = (const float*)d_in[2];   // [1024,1024]
    const float* Wk      = (const float*)d_in[3];   // [1024,1024]
    const float* wv      = (const float*)d_in[4];   // [1024,1]
    float* out = (float*)d_out;                     // [16,8192]

    cudaFuncSetAttribute(attn_kernel, cudaFuncAttributeMaxDynamicSharedMemorySize, SMEM_BYTES);

    round_permute_keys<<<8192, 256>>>((const float4*)keys);
    round_permute_wk<<<4096, 256>>>(Wk);
    qproj_kernel<<<dim3(H_ / 256, B_), 256>>>(queries, Wq);
    attn_kernel<<<M_TOTAL / TM, 256, SMEM_BYTES>>>(wv, out);
}

// round 9
// speedup vs baseline: 3.0911x; 2.3359x over previous
#include <cuda_runtime.h>
#include <cuda_fp16.h>
#include <cstdint>
#include <cstddef>

#define B_ 16
#define LK_ 8192
#define D_ 1024
#define H_ 1024
#define M_TOTAL (B_*LK_)

#define TM 64              // CTA rows
#define TN 128             // h-chunk width
#define TKS 32             // K per pipeline stage (2 x k16)
#define NCH (H_/TN)        // 8
#define KST (D_/TKS)       // 32
#define TOTS (NCH*KST)     // 256 stages
#define NSTAGE 4

// smem byte offsets
#define SM_A   0                          // NSTAGE * 4096 B (64x32 halves/stage)
#define SM_B   (NSTAGE*4096)              // NSTAGE * 8192 B (128x32 halves/stage)
#define SM_QP  (SM_A + NSTAGE*4096 + NSTAGE*8192)   // 49152
#define SM_WV  (SM_QP + TN*4)
#define SM_RED (SM_WV + TN*4)
#define SMEM_BYTES (SM_RED + TM*4*4)      // 51200

// ---- device scratch ----
__device__ float g_qp[B_*H_];
// keys as fp16 fragment images: [mtile(2048)][k16(64)][r16(4)][lane(32)] x 16B
__device__ __half g_keysH[(size_t)M_TOTAL * D_];          // 256 MB
// W_k as fp16 fragment images: [nc(8)][k16(64)][ndt(8)][lane(32)] x 16B
__device__ __half g_WkH[(size_t)D_ * H_];                 // 2 MB

// ---------------- helpers ----------------
__device__ __forceinline__ float tanh_hw(float x) {
    float r; asm("tanh.approx.f32 %0, %1;" : "=f"(r) : "f"(x)); return r;
}
__device__ __forceinline__ void cp16(void* dst, const void* src) {
    uint32_t d = (uint32_t)__cvta_generic_to_shared(dst);
    asm volatile("cp.async.cg.shared.global [%0], [%1], 16;\n" :: "r"(d), "l"(src));
}
__device__ __forceinline__ uint32_t h2u(__half2 h) {
    return *reinterpret_cast<uint32_t*>(&h);
}
__device__ __forceinline__ void mmaf16(float* c, uint4 a, uint32_t b0, uint32_t b1) {
    asm volatile(
        "mma.sync.aligned.m16n8k16.row.col.f32.f16.f16.f32 "
        "{%0,%1,%2,%3},{%4,%5,%6,%7},{%8,%9},{%0,%1,%2,%3};"
        : "+f"(c[0]), "+f"(c[1]), "+f"(c[2]), "+f"(c[3])
        : "r"(a.x), "r"(a.y), "r"(a.z), "r"(a.w), "r"(b0), "r"(b1));
}

// ---------------- prep: keys -> fp16 A-fragment images ----------------
// unit u = [mtile][k16][r16][lane]; thread gathers 4x float2, writes one 16B frag.
// frag = {h2(row g,k 2t..), h2(row g+8,k 2t..), h2(row g,k 2t+8..), h2(row g+8,k 2t+8..)}
__global__ __launch_bounds__(256) void prep_keys(const float* __restrict__ keys) {
    int u = blockIdx.x * 256 + threadIdx.x;      // 16,777,216 units
    int lane = u & 31;
    int r16  = (u >> 5) & 3;
    int k16  = (u >> 7) & 63;
    int mtile = u >> 13;
    int g = lane >> 2, t = lane & 3;
    const float* src = keys + ((size_t)(mtile * 64 + r16 * 16 + g)) * D_ + k16 * 16;
    float2 f00 = *(const float2*)(src + 2 * t);
    float2 f01 = *(const float2*)(src + 2 * t + 8);
    float2 f10 = *(const float2*)(src + 8 * D_ + 2 * t);
    float2 f11 = *(const float2*)(src + 8 * D_ + 2 * t + 8);
    uint4 v;
    v.x = h2u(__float22half2_rn(f00));
    v.y = h2u(__float22half2_rn(f10));
    v.z = h2u(__float22half2_rn(f01));
    v.w = h2u(__float22half2_rn(f11));
    ((uint4*)g_keysH)[u] = v;                    // dst index == u (layout matches)
}

// ---------------- prep: W_k -> fp16 B-fragment images ----------------
// unit u = [nc][k16][ndt][lane]; frag = {b0(n=g), b1(n=g), b0(n=g+8), b1(n=g+8)}
// b0 = {B[k0+2t][n], B[k0+2t+1][n]}, b1 = same at k+8; B[k][n] = Wk[k][h]
__global__ __launch_bounds__(256) void prep_wk(const float* __restrict__ Wk) {
    int u = blockIdx.x * 256 + threadIdx.x;      // 131,072 units
    int lane = u & 31;
    int ndt  = (u >> 5) & 7;
    int k16  = (u >> 8) & 63;
    int nc   = u >> 14;
    int g = lane >> 2, t = lane & 3;
    int h  = nc * 128 + ndt * 16 + g;
    int k0 = k16 * 16 + 2 * t;
    float2 f00 = make_float2(Wk[(size_t)k0 * H_ + h],       Wk[(size_t)(k0 + 1) * H_ + h]);
    float2 f01 = make_float2(Wk[(size_t)(k0 + 8) * H_ + h], Wk[(size_t)(k0 + 9) * H_ + h]);
    float2 f10 = make_float2(Wk[(size_t)k0 * H_ + h + 8],   Wk[(size_t)(k0 + 1) * H_ + h + 8]);
    float2 f11 = make_float2(Wk[(size_t)(k0 + 8) * H_ + h + 8], Wk[(size_t)(k0 + 9) * H_ + h + 8]);
    uint4 v;
    v.x = h2u(__float22half2_rn(f00));
    v.y = h2u(__float22half2_rn(f01));
    v.z = h2u(__float22half2_rn(f10));
    v.w = h2u(__float22half2_rn(f11));
    ((uint4*)g_WkH)[u] = v;
}

// ---------------- qp[b,h] = queries @ W_q (full fp32) ----------------
__global__ __launch_bounds__(256) void qproj_kernel(const float* __restrict__ q,
                                                    const float* __restrict__ Wq) {
    int b = blockIdx.y;
    int h = blockIdx.x * 256 + threadIdx.x;
    const float* qr = q + b * D_;
    float acc = 0.f;
#pragma unroll 8
    for (int d = 0; d < D_; ++d) acc = fmaf(qr[d], Wq[d * H_ + h], acc);
    g_qp[b * H_ + h] = acc;
}

// linear stage fill: A 4KB (1 cp16/thread), B 8KB (2 cp16/thread)
__device__ __forceinline__ void load_stage(char* smem, int mtile, int sn, int tid) {
    const __half* srcA = g_keysH + ((size_t)mtile * 64 + (size_t)(sn & 31) * 2) * 1024;
    const __half* srcB = g_WkH + ((size_t)((sn >> 5) * 64 + (sn & 31) * 2)) * 2048;
    __half* dA = (__half*)(smem + SM_A + (sn & (NSTAGE - 1)) * 4096);
    __half* dB = (__half*)(smem + SM_B + (sn & (NSTAGE - 1)) * 8192);
    cp16(dA + tid * 8,         srcA + tid * 8);
    cp16(dB + tid * 8,         srcB + tid * 8);
    cp16(dB + (tid + 256) * 8, srcB + (tid + 256) * 8);
}

// ---------------- fused keys@W_k -> tanh -> dot(w_v), fp16 tensor ----------------
__global__ void __launch_bounds__(256, 3) attn_kernel(const float* __restrict__ wv,
                                                      float* __restrict__ out) {
    extern __shared__ char smem[];
    float* s_qp  = (float*)(smem + SM_QP);
    float* s_wv  = (float*)(smem + SM_WV);
    float* s_red = (float*)(smem + SM_RED);

    const int tid  = threadIdx.x;
    const int lane = tid & 31, warp = tid >> 5;
    const int wm = warp >> 2, wn = warp & 3;        // 2(m) x 4(n) warp grid, warp tile 32x32
    const int g = lane >> 2, t = lane & 3;
    const int mtile = blockIdx.x;
    const int m_base = mtile * TM;
    const int b = mtile >> 7;                        // 128 tiles per batch

    float score = 0.f;
    if (tid < TN) { s_qp[tid] = g_qp[b * H_ + tid]; s_wv[tid] = wv[tid]; }

#pragma unroll
    for (int s = 0; s < NSTAGE - 1; ++s) {
        load_stage(smem, mtile, s, tid);
        asm volatile("cp.async.commit_group;\n");
    }

    float acc[2][2][2][4];                           // [mi][dt][nj][frag]
#pragma unroll
    for (int mi = 0; mi < 2; ++mi)
#pragma unroll
        for (int dt = 0; dt < 2; ++dt)
#pragma unroll
            for (int nj = 0; nj < 2; ++nj)
#pragma unroll
                for (int r = 0; r < 4; ++r) acc[mi][dt][nj][r] = 0.f;

    for (int s = 0; s < TOTS; ++s) {
        asm volatile("cp.async.wait_group %0;\n" :: "n"(NSTAGE - 2));
        __syncthreads();
        if (s + NSTAGE - 1 < TOTS) load_stage(smem, mtile, s + NSTAGE - 1, tid);
        asm volatile("cp.async.commit_group;\n");

        const char* sA = smem + SM_A + (s & (NSTAGE - 1)) * 4096;
        const char* sB = smem + SM_B + (s & (NSTAGE - 1)) * 8192;

#pragma unroll
        for (int k16 = 0; k16 < 2; ++k16) {
            uint4 a0 = *(const uint4*)(sA + k16 * 2048 + (wm * 2 + 0) * 512 + lane * 16);
            uint4 a1 = *(const uint4*)(sA + k16 * 2048 + (wm * 2 + 1) * 512 + lane * 16);
            uint4 bA = *(const uint4*)(sB + k16 * 4096 + (wn * 2 + 0) * 512 + lane * 16);
            uint4 bB = *(const uint4*)(sB + k16 * 4096 + (wn * 2 + 1) * 512 + lane * 16);
            mmaf16(acc[0][0][0], a0, bA.x, bA.y);
            mmaf16(acc[0][0][1], a0, bA.z, bA.w);
            mmaf16(acc[0][1][0], a0, bB.x, bB.y);
            mmaf16(acc[0][1][1], a0, bB.z, bB.w);
            mmaf16(acc[1][0][0], a1, bA.x, bA.y);
            mmaf16(acc[1][0][1], a1, bA.z, bA.w);
            mmaf16(acc[1][1][0], a1, bB.x, bB.y);
            mmaf16(acc[1][1][1], a1, bB.z, bB.w);
        }

        if ((s & 31) == 31) {
            const int nc = s >> 5;
#pragma unroll
            for (int mi = 0; mi < 2; ++mi) {
                float p0 = 0.f, p1 = 0.f;
#pragma unroll
                for (int dt = 0; dt < 2; ++dt)
#pragma unroll
                    for (int nj = 0; nj < 2; ++nj) {
                        int c0 = wn * 32 + dt * 16 + nj * 8 + 2 * t;
                        float q0 = s_qp[c0], q1 = s_qp[c0 + 1];
                        float w0 = s_wv[c0], w1 = s_wv[c0 + 1];
                        float* a = acc[mi][dt][nj];
                        p0 += tanh_hw(q0 + a[0]) * w0 + tanh_hw(q1 + a[1]) * w1;
                        p1 += tanh_hw(q0 + a[2]) * w0 + tanh_hw(q1 + a[3]) * w1;
                        a[0] = 0.f; a[1] = 0.f; a[2] = 0.f; a[3] = 0.f;
                    }
                p0 += __shfl_xor_sync(0xffffffffu, p0, 1);
                p0 += __shfl_xor_sync(0xffffffffu, p0, 2);
                p1 += __shfl_xor_sync(0xffffffffu, p1, 1);
                p1 += __shfl_xor_sync(0xffffffffu, p1, 2);
                if (t == 0) {
                    int r0 = wm * 32 + mi * 16 + g;
                    s_red[(r0    ) * 4 + wn] = p0;
                    s_red[(r0 + 8) * 4 + wn] = p1;
                }
            }
            __syncthreads();   // s_red ready; also fences the s_qp/s_wv reads above
            if (tid < TM)
                score += s_red[tid * 4 + 0] + s_red[tid * 4 + 1]
                       + s_red[tid * 4 + 2] + s_red[tid * 4 + 3];
            if (nc + 1 < NCH && tid < TN) {
                s_qp[tid] = g_qp[b * H_ + (nc + 1) * TN + tid];
                s_wv[tid] = wv[(nc + 1) * TN + tid];
            }
            // next-iteration top __syncthreads orders these writes vs readers
        }
    }

    asm volatile("cp.async.wait_group 0;\n");
    if (tid < TM) out[m_base + tid] = score;
}

// ---------------- launch ----------------
extern "C" void kernel_launch(void* const* d_in, const int* in_sizes, int n_in,
                              void* d_out, int out_size) {
    (void)in_sizes; (void)n_in; (void)out_size;
    const float* queries = (const float*)d_in[0];   // [16,1,1024]
    const float* keys    = (const float*)d_in[1];   // [16,8192,1024]
    const float* Wq      = (const float*)d_in[2];   // [1024,1024]
    const float* Wk      = (const float*)d_in[3];   // [1024,1024]
    const float* wv      = (const float*)d_in[4];   // [1024,1]
    float* out = (float*)d_out;                     // [16,8192]

    cudaFuncSetAttribute(attn_kernel, cudaFuncAttributeMaxDynamicSharedMemorySize, SMEM_BYTES);

    prep_keys<<<65536, 256>>>(keys);
    prep_wk<<<512, 256>>>(Wk);
    qproj_kernel<<<dim3(H_ / 256, B_), 256>>>(queries, Wq);
    attn_kernel<<<M_TOTAL / TM, 256, SMEM_BYTES>>>(wv, out);
}

// round 11
// speedup vs baseline: 3.5257x; 1.1406x over previous
#include <cuda_runtime.h>
#include <cuda_fp16.h>
#include <cstdint>
#include <cstddef>

#define B_ 16
#define LK_ 8192
#define D_ 1024
#define H_ 1024
#define M_TOTAL (B_*LK_)

#define TM 128             // CTA rows
#define TN 128             // h-chunk width
#define TKS 32             // K per pipeline stage (2 x k16)
#define NCH (H_/TN)        // 8
#define KST (D_/TKS)       // 32
#define TOTS (NCH*KST)     // 256 stages
#define NSTAGE 4

// smem byte offsets
#define SM_A   0                          // NSTAGE * 8192 B (128 rows x 32 k halves)
#define SM_B   (NSTAGE*8192)              // NSTAGE * 8192 B (128 cols x 32 k halves)
#define SM_QP  (SM_A + 2*NSTAGE*8192)     // 65536
#define SM_WV  (SM_QP + TN*4)
#define SM_RED (SM_WV + TN*4)
#define SMEM_BYTES (SM_RED + TM*4*4)      // 68608

// ---- device scratch ----
__device__ float g_qp[B_*H_];
// keys fp16 A-fragment images: [mtile(1024)][k16(64)][r16(8)][lane(32)] x 16B
__device__ __half g_keysH[(size_t)M_TOTAL * D_];          // 256 MB
// W_k fp16 B-fragment images: [nc(8)][k16(64)][ndt(8)][lane(32)] x 16B
__device__ __half g_WkH[(size_t)D_ * H_];                 // 2 MB

// ---------------- helpers ----------------
__device__ __forceinline__ float tanh_hw(float x) {
    float r; asm("tanh.approx.f32 %0, %1;" : "=f"(r) : "f"(x)); return r;
}
__device__ __forceinline__ void cp16(void* dst, const void* src) {
    uint32_t d = (uint32_t)__cvta_generic_to_shared(dst);
    asm volatile("cp.async.cg.shared.global [%0], [%1], 16;\n" :: "r"(d), "l"(src));
}
__device__ __forceinline__ uint32_t h2u(__half2 h) {
    return *reinterpret_cast<uint32_t*>(&h);
}
__device__ __forceinline__ void mmaf16(float* c, uint4 a, uint32_t b0, uint32_t b1) {
    asm volatile(
        "mma.sync.aligned.m16n8k16.row.col.f32.f16.f16.f32 "
        "{%0,%1,%2,%3},{%4,%5,%6,%7},{%8,%9},{%0,%1,%2,%3};"
        : "+f"(c[0]), "+f"(c[1]), "+f"(c[2]), "+f"(c[3])
        : "r"(a.x), "r"(a.y), "r"(a.z), "r"(a.w), "r"(b0), "r"(b1));
}

// ---------------- prep: keys -> fp16 A-fragment images (TM=128 layout) ----------------
// unit u = [mtile(1024)][k16(64)][r16(8)][lane(32)]; thread gathers 4x float2 -> one 16B frag
__global__ __launch_bounds__(256) void prep_keys(const float* __restrict__ keys) {
    int u = blockIdx.x * 256 + threadIdx.x;      // 16,777,216 units
    int lane = u & 31;
    int r16  = (u >> 5) & 7;
    int k16  = (u >> 8) & 63;
    int mtile = u >> 14;
    int g = lane >> 2, t = lane & 3;
    const float* src = keys + ((size_t)(mtile * 128 + r16 * 16 + g)) * D_ + k16 * 16;
    float2 f00 = *(const float2*)(src + 2 * t);
    float2 f01 = *(const float2*)(src + 2 * t + 8);
    float2 f10 = *(const float2*)(src + 8 * D_ + 2 * t);
    float2 f11 = *(const float2*)(src + 8 * D_ + 2 * t + 8);
    uint4 v;
    v.x = h2u(__float22half2_rn(f00));
    v.y = h2u(__float22half2_rn(f10));
    v.z = h2u(__float22half2_rn(f01));
    v.w = h2u(__float22half2_rn(f11));
    ((uint4*)g_keysH)[u] = v;
}

// ---------------- prep: W_k -> fp16 B-fragment images (unchanged layout) ----------------
__global__ __launch_bounds__(256) void prep_wk(const float* __restrict__ Wk) {
    int u = blockIdx.x * 256 + threadIdx.x;      // 131,072 units
    int lane = u & 31;
    int ndt  = (u >> 5) & 7;
    int k16  = (u >> 8) & 63;
    int nc   = u >> 14;
    int g = lane >> 2, t = lane & 3;
    int h  = nc * 128 + ndt * 16 + g;
    int k0 = k16 * 16 + 2 * t;
    float2 f00 = make_float2(Wk[(size_t)k0 * H_ + h],       Wk[(size_t)(k0 + 1) * H_ + h]);
    float2 f01 = make_float2(Wk[(size_t)(k0 + 8) * H_ + h], Wk[(size_t)(k0 + 9) * H_ + h]);
    float2 f10 = make_float2(Wk[(size_t)k0 * H_ + h + 8],   Wk[(size_t)(k0 + 1) * H_ + h + 8]);
    float2 f11 = make_float2(Wk[(size_t)(k0 + 8) * H_ + h + 8], Wk[(size_t)(k0 + 9) * H_ + h + 8]);
    uint4 v;
    v.x = h2u(__float22half2_rn(f00));
    v.y = h2u(__float22half2_rn(f01));
    v.z = h2u(__float22half2_rn(f10));
    v.w = h2u(__float22half2_rn(f11));
    ((uint4*)g_WkH)[u] = v;
}

// ---------------- qp[b,h] = queries @ W_q (split-D x4, fp32) ----------------
__global__ __launch_bounds__(256) void qproj_kernel(const float* __restrict__ q,
                                                    const float* __restrict__ Wq) {
    int b = blockIdx.y;
    int h = blockIdx.x * 64 + (threadIdx.x >> 2);
    int part = threadIdx.x & 3;
    const float* qr = q + b * D_;
    float acc = 0.f;
    int d0 = part * 256;
#pragma unroll 8
    for (int d = d0; d < d0 + 256; ++d) acc = fmaf(qr[d], Wq[(size_t)d * H_ + h], acc);
    acc += __shfl_xor_sync(0xffffffffu, acc, 1);
    acc += __shfl_xor_sync(0xffffffffu, acc, 2);
    if (part == 0) g_qp[b * H_ + h] = acc;
}

// linear stage fill: A 8KB (2 cp16/thread), B 8KB (2 cp16/thread)
__device__ __forceinline__ void load_stage(char* smem, int mtile, int sn, int tid) {
    const __half* srcA = g_keysH + ((size_t)mtile * 64 + (size_t)(sn & 31) * 2) * 2048;
    const __half* srcB = g_WkH + ((size_t)((sn >> 5) * 64 + (sn & 31) * 2)) * 2048;
    __half* dA = (__half*)(smem + SM_A + (sn & (NSTAGE - 1)) * 8192);
    __half* dB = (__half*)(smem + SM_B + (sn & (NSTAGE - 1)) * 8192);
    cp16(dA + tid * 8,         srcA + tid * 8);
    cp16(dA + (tid + 256) * 8, srcA + (tid + 256) * 8);
    cp16(dB + tid * 8,         srcB + tid * 8);
    cp16(dB + (tid + 256) * 8, srcB + (tid + 256) * 8);
}

// ---------------- fused keys@W_k -> tanh -> dot(w_v), fp16 tensor ----------------
__global__ void __launch_bounds__(256, 2) attn_kernel(const float* __restrict__ wv,
                                                      float* __restrict__ out) {
    extern __shared__ char smem[];
    float* s_qp  = (float*)(smem + SM_QP);
    float* s_wv  = (float*)(smem + SM_WV);
    float* s_red = (float*)(smem + SM_RED);

    const int tid  = threadIdx.x;
    const int lane = tid & 31, warp = tid >> 5;
    const int wm = warp >> 2, wn = warp & 3;        // 2(m) x 4(n) grid, warp tile 64x32
    const int g = lane >> 2, t = lane & 3;
    const int mtile = blockIdx.x;
    const int m_base = mtile * TM;
    const int b = mtile >> 6;                        // 64 tiles per batch

    float score = 0.f;
    if (tid < TN) { s_qp[tid] = g_qp[b * H_ + tid]; s_wv[tid] = wv[tid]; }

#pragma unroll
    for (int s = 0; s < NSTAGE - 1; ++s) {
        load_stage(smem, mtile, s, tid);
        asm volatile("cp.async.commit_group;\n");
    }

    float acc[4][2][2][4];                           // [mi][dt][nj][frag]
#pragma unroll
    for (int mi = 0; mi < 4; ++mi)
#pragma unroll
        for (int dt = 0; dt < 2; ++dt)
#pragma unroll
            for (int nj = 0; nj < 2; ++nj)
#pragma unroll
                for (int r = 0; r < 4; ++r) acc[mi][dt][nj][r] = 0.f;

    for (int s = 0; s < TOTS; ++s) {
        asm volatile("cp.async.wait_group %0;\n" :: "n"(NSTAGE - 2));
        __syncthreads();
        if (s + NSTAGE - 1 < TOTS) load_stage(smem, mtile, s + NSTAGE - 1, tid);
        asm volatile("cp.async.commit_group;\n");

        const char* sA = smem + SM_A + (s & (NSTAGE - 1)) * 8192;
        const char* sB = smem + SM_B + (s & (NSTAGE - 1)) * 8192;

#pragma unroll
        for (int k16 = 0; k16 < 2; ++k16) {
            uint4 bA = *(const uint4*)(sB + k16 * 4096 + (wn * 2 + 0) * 512 + lane * 16);
            uint4 bB = *(const uint4*)(sB + k16 * 4096 + (wn * 2 + 1) * 512 + lane * 16);
#pragma unroll
            for (int mi = 0; mi < 4; ++mi) {
                uint4 a = *(const uint4*)(sA + k16 * 4096 + (wm * 4 + mi) * 512 + lane * 16);
                mmaf16(acc[mi][0][0], a, bA.x, bA.y);
                mmaf16(acc[mi][0][1], a, bA.z, bA.w);
                mmaf16(acc[mi][1][0], a, bB.x, bB.y);
                mmaf16(acc[mi][1][1], a, bB.z, bB.w);
            }
        }

        if ((s & 31) == 31) {
            const int nc = s >> 5;
#pragma unroll
            for (int mi = 0; mi < 4; ++mi) {
                float p0 = 0.f, p1 = 0.f;
#pragma unroll
                for (int dt = 0; dt < 2; ++dt)
#pragma unroll
                    for (int nj = 0; nj < 2; ++nj) {
                        int c0 = wn * 32 + dt * 16 + nj * 8 + 2 * t;
                        float q0 = s_qp[c0], q1 = s_qp[c0 + 1];
                        float w0 = s_wv[c0], w1 = s_wv[c0 + 1];
                        float* a = acc[mi][dt][nj];
                        p0 += tanh_hw(q0 + a[0]) * w0 + tanh_hw(q1 + a[1]) * w1;
                        p1 += tanh_hw(q0 + a[2]) * w0 + tanh_hw(q1 + a[3]) * w1;
                        a[0] = 0.f; a[1] = 0.f; a[2] = 0.f; a[3] = 0.f;
                    }
                p0 += __shfl_xor_sync(0xffffffffu, p0, 1);
                p0 += __shfl_xor_sync(0xffffffffu, p0, 2);
                p1 += __shfl_xor_sync(0xffffffffu, p1, 1);
                p1 += __shfl_xor_sync(0xffffffffu, p1, 2);
                if (t == 0) {
                    int r0 = wm * 64 + mi * 16 + g;
                    s_red[(r0    ) * 4 + wn] = p0;
                    s_red[(r0 + 8) * 4 + wn] = p1;
                }
            }
            __syncthreads();   // s_red ready; also fences s_qp/s_wv reads above
            if (tid < TM)
                score += s_red[tid * 4 + 0] + s_red[tid * 4 + 1]
                       + s_red[tid * 4 + 2] + s_red[tid * 4 + 3];
            if (nc + 1 < NCH && tid < TN) {
                s_qp[tid] = g_qp[b * H_ + (nc + 1) * TN + tid];
                s_wv[tid] = wv[(nc + 1) * TN + tid];
            }
            // next-iteration top __syncthreads orders these writes vs readers
        }
    }

    asm volatile("cp.async.wait_group 0;\n");
    if (tid < TM) out[m_base + tid] = score;
}

// ---------------- launch ----------------
extern "C" void kernel_launch(void* const* d_in, const int* in_sizes, int n_in,
                              void* d_out, int out_size) {
    (void)in_sizes; (void)n_in; (void)out_size;
    const float* queries = (const float*)d_in[0];   // [16,1,1024]
    const float* keys    = (const float*)d_in[1];   // [16,8192,1024]
    const float* Wq      = (const float*)d_in[2];   // [1024,1024]
    const float* Wk      = (const float*)d_in[3];   // [1024,1024]
    const float* wv      = (const float*)d_in[4];   // [1024,1]
    float* out = (float*)d_out;                     // [16,8192]

    cudaFuncSetAttribute(attn_kernel, cudaFuncAttributeMaxDynamicSharedMemorySize, SMEM_BYTES);

    prep_keys<<<65536, 256>>>(keys);
    prep_wk<<<512, 256>>>(Wk);
    qproj_kernel<<<dim3(H_ / 64, B_), 256>>>(queries, Wq);
    attn_kernel<<<M_TOTAL / TM, 256, SMEM_BYTES>>>(wv, out);
}

// round 12
// speedup vs baseline: 3.5975x; 1.0204x over previous
#include <cuda_runtime.h>
#include <cuda_fp16.h>
#include <cstdint>
#include <cstddef>

#define B_ 16
#define LK_ 8192
#define D_ 1024
#define H_ 1024
#define M_TOTAL (B_*LK_)

#define TM 128             // CTA rows
#define TN 128             // h-chunk width
#define TKS 64             // K per pipeline stage (4 x k16)
#define NCH (H_/TN)        // 8
#define KST (D_/TKS)       // 16
#define TOTS (NCH*KST)     // 128 stages
#define NSTAGE 3
#define A_STG_BYTES 16384  // 4 k16 x 8 r16 x 32 lane x 16B

// smem byte offsets
#define SM_A   0
#define SM_QP  (NSTAGE*A_STG_BYTES)       // 49152
#define SM_WV  (SM_QP + TN*4)
#define SM_RED (SM_WV + TN*4)
#define SMEM_BYTES (SM_RED + TM*4*4)      // 52224

// ---- device scratch ----
__device__ float g_qp[B_*H_];
// keys fp16 A-fragment images: [mtile(1024)][k16(64)][r16(8)][lane(32)] x 16B
__device__ __half g_keysH[(size_t)M_TOTAL * D_];          // 256 MB
// W_k fp16 B-fragment images: [gh(512)=nc*64+k16][ndt(8)][lane(32)] x 16B
__device__ __half g_WkH[(size_t)D_ * H_];                 // 2 MB

// ---------------- helpers ----------------
__device__ __forceinline__ float tanh_hw(float x) {
    float r; asm("tanh.approx.f32 %0, %1;" : "=f"(r) : "f"(x)); return r;
}
__device__ __forceinline__ void cp16(void* dst, const void* src) {
    uint32_t d = (uint32_t)__cvta_generic_to_shared(dst);
    asm volatile("cp.async.cg.shared.global [%0], [%1], 16;\n" :: "r"(d), "l"(src));
}
__device__ __forceinline__ uint32_t h2u(__half2 h) {
    return *reinterpret_cast<uint32_t*>(&h);
}
__device__ __forceinline__ void mmaf16(float* c, uint4 a, uint32_t b0, uint32_t b1) {
    asm volatile(
        "mma.sync.aligned.m16n8k16.row.col.f32.f16.f16.f32 "
        "{%0,%1,%2,%3},{%4,%5,%6,%7},{%8,%9},{%0,%1,%2,%3};"
        : "+f"(c[0]), "+f"(c[1]), "+f"(c[2]), "+f"(c[3])
        : "r"(a.x), "r"(a.y), "r"(a.z), "r"(a.w), "r"(b0), "r"(b1));
}

// ---------------- prep: keys -> fp16 A-fragment images ----------------
__global__ __launch_bounds__(256) void prep_keys(const float* __restrict__ keys) {
    int u = blockIdx.x * 256 + threadIdx.x;      // 16,777,216 units
    int lane = u & 31;
    int r16  = (u >> 5) & 7;
    int k16  = (u >> 8) & 63;
    int mtile = u >> 14;
    int g = lane >> 2, t = lane & 3;
    const float* src = keys + ((size_t)(mtile * 128 + r16 * 16 + g)) * D_ + k16 * 16;
    float2 f00 = *(const float2*)(src + 2 * t);
    float2 f01 = *(const float2*)(src + 2 * t + 8);
    float2 f10 = *(const float2*)(src + 8 * D_ + 2 * t);
    float2 f11 = *(const float2*)(src + 8 * D_ + 2 * t + 8);
    uint4 v;
    v.x = h2u(__float22half2_rn(f00));
    v.y = h2u(__float22half2_rn(f10));
    v.z = h2u(__float22half2_rn(f01));
    v.w = h2u(__float22half2_rn(f11));
    ((uint4*)g_keysH)[u] = v;
}

// ---------------- prep: W_k -> fp16 B-fragment images ----------------
__global__ __launch_bounds__(256) void prep_wk(const float* __restrict__ Wk) {
    int u = blockIdx.x * 256 + threadIdx.x;      // 131,072 units
    int lane = u & 31;
    int ndt  = (u >> 5) & 7;
    int k16  = (u >> 8) & 63;
    int nc   = u >> 14;
    int g = lane >> 2, t = lane & 3;
    int h  = nc * 128 + ndt * 16 + g;
    int k0 = k16 * 16 + 2 * t;
    float2 f00 = make_float2(Wk[(size_t)k0 * H_ + h],       Wk[(size_t)(k0 + 1) * H_ + h]);
    float2 f01 = make_float2(Wk[(size_t)(k0 + 8) * H_ + h], Wk[(size_t)(k0 + 9) * H_ + h]);
    float2 f10 = make_float2(Wk[(size_t)k0 * H_ + h + 8],   Wk[(size_t)(k0 + 1) * H_ + h + 8]);
    float2 f11 = make_float2(Wk[(size_t)(k0 + 8) * H_ + h + 8], Wk[(size_t)(k0 + 9) * H_ + h + 8]);
    uint4 v;
    v.x = h2u(__float22half2_rn(f00));
    v.y = h2u(__float22half2_rn(f01));
    v.z = h2u(__float22half2_rn(f10));
    v.w = h2u(__float22half2_rn(f11));
    ((uint4*)g_WkH)[u] = v;
}

// ---------------- qp[b,h] = queries @ W_q (split-D x4, fp32) ----------------
__global__ __launch_bounds__(256) void qproj_kernel(const float* __restrict__ q,
                                                    const float* __restrict__ Wq) {
    int b = blockIdx.y;
    int h = blockIdx.x * 64 + (threadIdx.x >> 2);
    int part = threadIdx.x & 3;
    const float* qr = q + b * D_;
    float acc = 0.f;
    int d0 = part * 256;
#pragma unroll 8
    for (int d = d0; d < d0 + 256; ++d) acc = fmaf(qr[d], Wq[(size_t)d * H_ + h], acc);
    acc += __shfl_xor_sync(0xffffffffu, acc, 1);
    acc += __shfl_xor_sync(0xffffffffu, acc, 2);
    if (part == 0) g_qp[b * H_ + h] = acc;
}

// A-only stage fill: 16KB = 4 cp16/thread
__device__ __forceinline__ void load_stageA(char* smem, int mtile, int sn, int slot, int tid) {
    const __half* srcA = g_keysH + ((size_t)mtile * 64 + (size_t)(sn & 15) * 4) * 2048;
    __half* dA = (__half*)(smem + SM_A + slot * A_STG_BYTES);
#pragma unroll
    for (int i = 0; i < 4; ++i)
        cp16(dA + (tid + i * 256) * 8, srcA + (tid + i * 256) * 8);
}

// ---------------- fused keys@W_k -> tanh -> dot(w_v), fp16 tensor ----------------
__global__ void __launch_bounds__(256, 2) attn_kernel(const float* __restrict__ wv,
                                                      float* __restrict__ out) {
    extern __shared__ char smem[];
    float* s_qp  = (float*)(smem + SM_QP);
    float* s_wv  = (float*)(smem + SM_WV);
    float* s_red = (float*)(smem + SM_RED);

    const int tid  = threadIdx.x;
    const int lane = tid & 31, warp = tid >> 5;
    const int wm = warp >> 2, wn = warp & 3;        // 2(m) x 4(n) grid, warp tile 64x32
    const int g = lane >> 2, t = lane & 3;
    const int mtile = blockIdx.x;
    const int m_base = mtile * TM;
    const int b = mtile >> 6;                        // 64 tiles per batch

    const uint4* __restrict__ WkB = ((const uint4*)g_WkH) + (size_t)wn * 2 * 32 + lane;

    float score = 0.f;
    if (tid < TN) { s_qp[tid] = g_qp[b * H_ + tid]; s_wv[tid] = wv[tid]; }

    // A pipeline prologue: stages 0,1
    load_stageA(smem, mtile, 0, 0, tid);
    asm volatile("cp.async.commit_group;\n");
    load_stageA(smem, mtile, 1, 1, tid);
    asm volatile("cp.async.commit_group;\n");

    // B register prologue: halves gh=0 (current) and gh=1 (next)
    uint4 Bc0 = __ldg(WkB);            // gh=0, ndt=wn*2
    uint4 Bc1 = __ldg(WkB + 32);       // gh=0, ndt=wn*2+1
    uint4 Bn0 = __ldg(WkB + 256);      // gh=1
    uint4 Bn1 = __ldg(WkB + 288);

    float acc[4][2][2][4];
#pragma unroll
    for (int mi = 0; mi < 4; ++mi)
#pragma unroll
        for (int dt = 0; dt < 2; ++dt)
#pragma unroll
            for (int nj = 0; nj < 2; ++nj)
#pragma unroll
                for (int r = 0; r < 4; ++r) acc[mi][dt][nj][r] = 0.f;

    int slot = 0;          // rotating smem slot of current stage
    int slot_nx = 2;       // slot receiving stage s+2

    for (int s = 0; s < TOTS; ++s) {
        asm volatile("cp.async.wait_group %0;\n" :: "n"(NSTAGE - 2));
        __syncthreads();
        if (s + 2 < TOTS) load_stageA(smem, mtile, s + 2, slot_nx, tid);
        asm volatile("cp.async.commit_group;\n");

        const char* sA = smem + SM_A + slot * A_STG_BYTES;

#pragma unroll
        for (int h = 0; h < 4; ++h) {
            uint4 bA = Bc0, bB = Bc1;
            Bc0 = Bn0; Bc1 = Bn1;
            int gh2 = s * 4 + h + 2;
            if (gh2 > 511) gh2 = 511;
            const uint4* bp = WkB + (size_t)gh2 * 256;
            Bn0 = __ldg(bp);
            Bn1 = __ldg(bp + 32);
#pragma unroll
            for (int mi = 0; mi < 4; ++mi) {
                uint4 a = *(const uint4*)(sA + (h * 8 + wm * 4 + mi) * 512 + lane * 16);
                mmaf16(acc[mi][0][0], a, bA.x, bA.y);
                mmaf16(acc[mi][0][1], a, bA.z, bA.w);
                mmaf16(acc[mi][1][0], a, bB.x, bB.y);
                mmaf16(acc[mi][1][1], a, bB.z, bB.w);
            }
        }

        if ((s & 15) == 15) {
            const int nc = s >> 4;
#pragma unroll
            for (int mi = 0; mi < 4; ++mi) {
                float p0 = 0.f, p1 = 0.f;
#pragma unroll
                for (int dt = 0; dt < 2; ++dt)
#pragma unroll
                    for (int nj = 0; nj < 2; ++nj) {
                        int c0 = wn * 32 + dt * 16 + nj * 8 + 2 * t;
                        float q0 = s_qp[c0], q1 = s_qp[c0 + 1];
                        float w0 = s_wv[c0], w1 = s_wv[c0 + 1];
                        float* a = acc[mi][dt][nj];
                        p0 += tanh_hw(q0 + a[0]) * w0 + tanh_hw(q1 + a[1]) * w1;
                        p1 += tanh_hw(q0 + a[2]) * w0 + tanh_hw(q1 + a[3]) * w1;
                        a[0] = 0.f; a[1] = 0.f; a[2] = 0.f; a[3] = 0.f;
                    }
                p0 += __shfl_xor_sync(0xffffffffu, p0, 1);
                p0 += __shfl_xor_sync(0xffffffffu, p0, 2);
                p1 += __shfl_xor_sync(0xffffffffu, p1, 1);
                p1 += __shfl_xor_sync(0xffffffffu, p1, 2);
                if (t == 0) {
                    int r0 = wm * 64 + mi * 16 + g;
                    s_red[(r0    ) * 4 + wn] = p0;
                    s_red[(r0 + 8) * 4 + wn] = p1;
                }
            }
            __syncthreads();   // s_red ready; also fences s_qp/s_wv reads above
            if (tid < TM)
                score += s_red[tid * 4 + 0] + s_red[tid * 4 + 1]
                       + s_red[tid * 4 + 2] + s_red[tid * 4 + 3];
            if (nc + 1 < NCH && tid < TN) {
                s_qp[tid] = g_qp[b * H_ + (nc + 1) * TN + tid];
                s_wv[tid] = wv[(nc + 1) * TN + tid];
            }
            // next-iteration top __syncthreads orders these writes vs readers
        }

        slot = (slot == NSTAGE - 1) ? 0 : slot + 1;
        slot_nx = (slot_nx == NSTAGE - 1) ? 0 : slot_nx + 1;
    }

    asm volatile("cp.async.wait_group 0;\n");
    if (tid < TM) out[m_base + tid] = score;
}

// ---------------- launch ----------------
extern "C" void kernel_launch(void* const* d_in, const int* in_sizes, int n_in,
                              void* d_out, int out_size) {
    (void)in_sizes; (void)n_in; (void)out_size;
    const float* queries = (const float*)d_in[0];   // [16,1,1024]
    const float* keys    = (const float*)d_in[1];   // [16,8192,1024]
    const float* Wq      = (const float*)d_in[2];   // [1024,1024]
    const float* Wk      = (const float*)d_in[3];   // [1024,1024]
    const float* wv      = (const float*)d_in[4];   // [1024,1]
    float* out = (float*)d_out;                     // [16,8192]

    cudaFuncSetAttribute(attn_kernel, cudaFuncAttributeMaxDynamicSharedMemorySize, SMEM_BYTES);

    prep_keys<<<65536, 256>>>(keys);
    prep_wk<<<512, 256>>>(Wk);
    qproj_kernel<<<dim3(H_ / 64, B_), 256>>>(queries, Wq);
    attn_kernel<<<M_TOTAL / TM, 256, SMEM_BYTES>>>(wv, out);
}